// round 14
// baseline (speedup 1.0000x reference)
#include <cuda_runtime.h>
#include <cuda_bf16.h>
#include <math.h>

#define HID   256
#define NHEAD 8
#define VDIM  32
#define BATCH 8
#define NI    4096
#define NL    1024
#define NO    4096
#define CAP   512
#define NBLK  4

// f32 scratch
__device__ float g_bufA[BATCH * NI * HID];
__device__ float g_bufB[BATCH * NI * HID];
__device__ float g_la[BATCH * NL * HID];
// bf16 hi/lo planes
#define WSLOTS 19
__device__ __nv_bfloat16 g_whi[WSLOTS * HID * HID];
__device__ __nv_bfloat16 g_wlo[WSLOTS * HID * HID];
__device__ __nv_bfloat16 g_Ahi[BATCH * NI * HID];
__device__ __nv_bfloat16 g_Alo[BATCH * NI * HID];
__device__ __nv_bfloat16 g_lbhi[BATCH * NL * HID];
__device__ __nv_bfloat16 g_lblo[BATCH * NL * HID];
__device__ __nv_bfloat16 g_lchi[BATCH * NL * HID];
__device__ __nv_bfloat16 g_lclo[BATCH * NL * HID];
__device__ __nv_bfloat16 g_lhhi[BATCH * NL * HID];
__device__ __nv_bfloat16 g_lhlo[BATCH * NL * HID];
__device__ __nv_bfloat16 g_ldhi[BATCH * NL * HID];
__device__ __nv_bfloat16 g_ldlo[BATCH * NL * HID];
// masks / tables
__device__ int   g_idx_d[NL * CAP];
__device__ float g_dst_d[NL * CAP];
__device__ int   g_cnt_d[NL];
__device__ int   g_idx_p[NL * CAP];
__device__ float g_dst_p[NL * CAP];
__device__ int   g_cnt_p[NL];
__device__ float g_ex[NHEAD * 64 * 32];
__device__ float g_ey[NHEAD * 64 * 32];
__device__ float g_rsx[NHEAD * 64];
__device__ float g_rsy[NHEAD * 64];

__device__ __forceinline__ float gelu_f(float x) {
    float t = tanhf(0.7978845608028654f * (x + 0.044715f * x * x * x));
    return 0.5f * x * (1.0f + t);
}

__device__ __forceinline__ float head_scale(const float* r, int h) {
    float arg = 0.78539808485763197f * (1.0f + sinf(r[h]));
    return (float)tan((double)arg);
}

__device__ __forceinline__ void wr_planes(__nv_bfloat16* hi, __nv_bfloat16* lo,
                                          size_t idx, float v) {
    __nv_bfloat16 h = __float2bfloat16(v);
    hi[idx] = h;
    lo[idx] = __float2bfloat16(v - __bfloat162float(h));
}

__device__ __forceinline__ void mma16(float* c, const unsigned* a, const unsigned* b) {
    asm volatile(
        "mma.sync.aligned.m16n8k16.row.col.f32.bf16.bf16.f32 "
        "{%0,%1,%2,%3},{%4,%5,%6,%7},{%8,%9},{%0,%1,%2,%3};"
        : "+f"(c[0]), "+f"(c[1]), "+f"(c[2]), "+f"(c[3])
        : "r"(a[0]), "r"(a[1]), "r"(a[2]), "r"(a[3]), "r"(b[0]), "r"(b[1]));
}

__device__ __forceinline__ void ldm_x4(unsigned* r, unsigned addr) {
    asm volatile("ldmatrix.sync.aligned.m8n8.x4.shared.b16 {%0,%1,%2,%3}, [%4];"
        : "=r"(r[0]), "=r"(r[1]), "=r"(r[2]), "=r"(r[3]) : "r"(addr));
}

__device__ __forceinline__ void cp16(__nv_bfloat16* dst, const __nv_bfloat16* src) {
    unsigned d = (unsigned)__cvta_generic_to_shared(dst);
    asm volatile("cp.async.cg.shared.global [%0], [%1], 16;" :: "r"(d), "l"(src));
}
#define CP_COMMIT() asm volatile("cp.async.commit_group;")
#define CP_WAIT(N)  asm volatile("cp.async.wait_group %0;" :: "n"(N))

// ---------------- fused init: weight conversion + encoder -------------------
#define WB (WSLOTS * 65536 / 256)
__global__ void k_init(const float* __restrict__ down_w, const float* __restrict__ pa_w,
                       const float* __restrict__ up_w, const float* __restrict__ mlp1_w,
                       const float* __restrict__ mlp2_w, const float* __restrict__ res_w,
                       const float* __restrict__ de1w,
                       __nv_bfloat16* __restrict__ whi, __nv_bfloat16* __restrict__ wlo,
                       const float* __restrict__ x, const float* __restrict__ enw,
                       const float* __restrict__ enb, float* __restrict__ enc_out,
                       __nv_bfloat16* __restrict__ ohi, __nv_bfloat16* __restrict__ olo) {
    if (blockIdx.x < WB) {
        int idx = blockIdx.x * 256 + threadIdx.x;
        int slot = idx >> 16;
        int e = idx & 65535;
        int n = e >> 8, k = e & 255;
        float v;
        if (slot == 0)      v = down_w[(n >> 5) * 8192 + k * 32 + (n & 31)];
        else if (slot <= 4) v = pa_w[(slot - 1) * 65536 + (n >> 5) * 8192 + k * 32 + (n & 31)];
        else if (slot == 5) v = up_w[(n >> 5) * 8192 + k * 32 + (n & 31)];
        else if (slot <= 9) v = mlp1_w[(slot - 6) * 65536 + e];
        else if (slot <= 13) v = mlp2_w[(slot - 10) * 65536 + e];
        else if (slot <= 17) v = res_w[(slot - 14) * 65536 + e];
        else                v = de1w[e];
        wr_planes(whi, wlo, idx, v);
    } else {
        size_t idx = (size_t)(blockIdx.x - WB) * 256 + threadIdx.x;
        size_t row = idx >> 8;
        int o = (int)(idx & 255);
        float acc = enb[o];
#pragma unroll
        for (int i = 0; i < 4; i++) acc = fmaf(x[row * 4 + i], enw[o * 4 + i], acc);
        float v = gelu_f(acc);
        enc_out[idx] = v;
        wr_planes(ohi, olo, idx, v);
    }
}

// -------- percentile threshold + survivor lists ------------------------------
template <int NK, int QRES, int KRES, int QM, int MAXD2>
__global__ void k_thresh(float invden, int k0, float frac,
                         int* __restrict__ idxL, float* __restrict__ dstL,
                         int* __restrict__ cnt) {
    __shared__ int hist[MAXD2 + 1];
    __shared__ int pre[256];
    __shared__ int s_lo, s_hi;
    __shared__ float s_thr;
    int q = blockIdx.x, tid = threadIdx.x;
    int qa = (q % QRES) * QM, qb = (q / QRES) * QM;
    for (int i = tid; i <= MAXD2; i += 256) hist[i] = 0;
    __syncthreads();
    for (int k = tid; k < NK; k += 256) {
        int a = qa - (k % KRES), b = qb - (k / KRES);
        atomicAdd(&hist[a * a + b * b], 1);
    }
    __syncthreads();
    const int len = (MAXD2 + 256) / 256;
    int s0 = tid * len;
    int e0 = s0 + len; if (e0 > MAXD2 + 1) e0 = MAXD2 + 1;
    int loc = 0;
    for (int i = s0; i < e0; i++) loc += hist[i];
    pre[tid] = loc;
    __syncthreads();
    for (int ofs = 1; ofs < 256; ofs <<= 1) {
        int v = (tid >= ofs) ? pre[tid - ofs] : 0;
        __syncthreads();
        pre[tid] += v;
        __syncthreads();
    }
    int incl = pre[tid], excl = incl - loc;
    int t1 = k0 + 1, t2 = k0 + 2;
    if (excl < t1 && incl >= t1) {
        int c = excl;
        for (int i = s0; i < e0; i++) { c += hist[i]; if (c >= t1) { s_lo = i; break; } }
    }
    if (excl < t2 && incl >= t2) {
        int c = excl;
        for (int i = s0; i < e0; i++) { c += hist[i]; if (c >= t2) { s_hi = i; break; } }
    }
    __syncthreads();
    if (tid == 0) {
        float flo = (float)s_lo * invden, fhi = (float)s_hi * invden;
        s_thr = flo + frac * (fhi - flo);
    }
    __syncthreads();
    if (tid < 32) {
        int lane = tid, c = 0;
        float thr = s_thr;
        for (int base = 0; base < NK; base += 32) {
            int k = base + lane;
            int a = qa - (k % KRES), b = qb - (k / KRES);
            float m = (float)(a * a + b * b) * invden;
            bool p = (m <= thr);
            unsigned mb = __ballot_sync(0xffffffffu, p);
            if (p) {
                int pos = c + __popc(mb & ((1u << lane) - 1u));
                if (pos < CAP) { idxL[q * CAP + pos] = k; dstL[q * CAP + pos] = m; }
            }
            c += __popc(mb);
        }
        if (lane == 0) cnt[q] = (c < CAP) ? c : CAP;
    }
}

// ---------------- sparse masked attention: 8-way ILP gather -------------------
__global__ __launch_bounds__(256) void k_att_sparse(
    const float* __restrict__ value, const float* __restrict__ r,
    const int* __restrict__ idxL, const float* __restrict__ dstL,
    const int* __restrict__ cnt, __nv_bfloat16* __restrict__ ohi,
    __nv_bfloat16* __restrict__ olo, int NK_, int NQ_) {
    int q = blockIdx.x, h = blockIdx.y, tid = threadIdx.x;
    int n = cnt[q];
    float scale = head_scale(r, h);
    __shared__ float w_s[CAP];
    __shared__ int   i_s[CAP];
    __shared__ float red[256];
    float lsum = 0.0f;
    for (int j = tid; j < n; j += 256) {
        float e = expf(-__fmul_rn(dstL[q * CAP + j], scale));
        w_s[j] = e;
        i_s[j] = idxL[q * CAP + j];
        lsum += e;
    }
    red[tid] = lsum;
    __syncthreads();
    for (int s = 128; s > 0; s >>= 1) {
        if (tid < s) red[tid] += red[tid + s];
        __syncthreads();
    }
    float rden = 1.0f / red[0];
    int b = tid >> 5, v = tid & 31;
    const float* vb = value + (size_t)b * NK_ * HID + h * VDIM + v;
    float a0 = 0.f, a1 = 0.f, a2 = 0.f, a3 = 0.f;
    float a4 = 0.f, a5 = 0.f, a6 = 0.f, a7 = 0.f;
    int j = 0;
    for (; j + 8 <= n; j += 8) {
        // prefetch weights+indices first so the 8 LDGs batch at the front
        float w0 = w_s[j + 0], w1 = w_s[j + 1], w2 = w_s[j + 2], w3 = w_s[j + 3];
        float w4 = w_s[j + 4], w5 = w_s[j + 5], w6 = w_s[j + 6], w7 = w_s[j + 7];
        int i0 = i_s[j + 0], i1 = i_s[j + 1], i2 = i_s[j + 2], i3 = i_s[j + 3];
        int i4 = i_s[j + 4], i5 = i_s[j + 5], i6 = i_s[j + 6], i7 = i_s[j + 7];
        float v0 = vb[(size_t)i0 * HID];
        float v1 = vb[(size_t)i1 * HID];
        float v2 = vb[(size_t)i2 * HID];
        float v3 = vb[(size_t)i3 * HID];
        float v4 = vb[(size_t)i4 * HID];
        float v5 = vb[(size_t)i5 * HID];
        float v6 = vb[(size_t)i6 * HID];
        float v7 = vb[(size_t)i7 * HID];
        a0 = fmaf(w0, v0, a0); a1 = fmaf(w1, v1, a1);
        a2 = fmaf(w2, v2, a2); a3 = fmaf(w3, v3, a3);
        a4 = fmaf(w4, v4, a4); a5 = fmaf(w5, v5, a5);
        a6 = fmaf(w6, v6, a6); a7 = fmaf(w7, v7, a7);
    }
    for (; j < n; j++) a0 = fmaf(w_s[j], vb[(size_t)i_s[j] * HID], a0);
    float acc = ((a0 + a1) + (a2 + a3)) + ((a4 + a5) + (a6 + a7));
    float vout = gelu_f(acc * rden);
    size_t oidx = ((size_t)(b * NQ_ + q)) * HID + h * VDIM + v;
    wr_planes(ohi, olo, oidx, vout);
}

// ---------------- up attention tables -----------------------------------------
__global__ void k_up_exp(const float* __restrict__ r, float* __restrict__ ex,
                         float* __restrict__ ey, float* __restrict__ rsx,
                         float* __restrict__ rsy) {
    int h = blockIdx.x, tid = threadIdx.x;
    float scale = head_scale(r, h);
    for (int e = tid; e < 2048; e += 256) {
        int i = e >> 5, j = e & 31;
        int d = i - 2 * j, mn = i & 1;
        float v = expf(__fmul_rn((float)(mn - d * d) * (1.0f / 8192.0f), scale));
        ex[h * 2048 + e] = v;
        ey[h * 2048 + e] = v;
    }
    __syncthreads();
    if (tid < 64) {
        float s = 0.0f;
        for (int j = 0; j < 32; j++) s += ex[h * 2048 + tid * 32 + j];
        rsx[h * 64 + tid] = s;
        rsy[h * 64 + tid] = s;
    }
}

// Stage 1: contract ky
__global__ __launch_bounds__(256) void k_up_s1(const float* __restrict__ value,
                                               const float* __restrict__ ey,
                                               float* __restrict__ G1) {
    int kx = blockIdx.x, h = blockIdx.y, tid = threadIdx.x;
    __shared__ float eys[64][32];
    __shared__ float vs[32][256];
    for (int e = tid; e < 2048; e += 256) eys[e >> 5][e & 31] = ey[h * 2048 + e];
    int b = tid >> 5, v = tid & 31;
    const float* vp = value + ((size_t)b * NL + kx) * HID + h * VDIM + v;
#pragma unroll
    for (int ky = 0; ky < 32; ky++) vs[ky][tid] = vp[(size_t)ky * 32 * HID];
    __syncthreads();
    float* gp = G1 + ((size_t)h * 64 * 32 + kx) * 256 + tid;
#pragma unroll
    for (int qy = 0; qy < 64; qy += 4) {
        float a0 = 0.f, a1 = 0.f, a2 = 0.f, a3 = 0.f;
#pragma unroll
        for (int ky = 0; ky < 32; ky++) {
            float vv = vs[ky][tid];
            a0 = fmaf(eys[qy + 0][ky], vv, a0);
            a1 = fmaf(eys[qy + 1][ky], vv, a1);
            a2 = fmaf(eys[qy + 2][ky], vv, a2);
            a3 = fmaf(eys[qy + 3][ky], vv, a3);
        }
        gp[(size_t)(qy + 0) * 32 * 256] = a0;
        gp[(size_t)(qy + 1) * 32 * 256] = a1;
        gp[(size_t)(qy + 2) * 32 * 256] = a2;
        gp[(size_t)(qy + 3) * 32 * 256] = a3;
    }
}

// Stage 2: contract kx (plane output)
__global__ __launch_bounds__(256) void k_up_s2(const float* __restrict__ G1,
                                               const float* __restrict__ ex,
                                               const float* __restrict__ rsx,
                                               const float* __restrict__ rsy,
                                               __nv_bfloat16* __restrict__ ohi,
                                               __nv_bfloat16* __restrict__ olo) {
    int qy = blockIdx.x, h = blockIdx.y, tid = threadIdx.x;
    __shared__ float exs[64][32];
    __shared__ float gs[32][256];
    for (int e = tid; e < 2048; e += 256) exs[e >> 5][e & 31] = ex[h * 2048 + e];
    const float* gb = G1 + (size_t)(h * 64 + qy) * 32 * 256;
    for (int e = tid; e < 32 * 256; e += 256) gs[e >> 8][e & 255] = gb[e];
    __syncthreads();
    int b = tid >> 5, v = tid & 31;
    float sy = rsy[h * 64 + qy];
#pragma unroll
    for (int qx = 0; qx < 64; qx += 4) {
        float a0 = 0.f, a1 = 0.f, a2 = 0.f, a3 = 0.f;
#pragma unroll
        for (int kx = 0; kx < 32; kx++) {
            float g = gs[kx][tid];
            a0 = fmaf(exs[qx + 0][kx], g, a0);
            a1 = fmaf(exs[qx + 1][kx], g, a1);
            a2 = fmaf(exs[qx + 2][kx], g, a2);
            a3 = fmaf(exs[qx + 3][kx], g, a3);
        }
#pragma unroll
        for (int i = 0; i < 4; i++) {
            float acc = (i == 0) ? a0 : (i == 1) ? a1 : (i == 2) ? a2 : a3;
            float rdv = 1.0f / (rsx[h * 64 + qx + i] * sy);
            float vout = gelu_f(acc * rdv);
            size_t oidx = ((size_t)b * NO + qy * 64 + qx + i) * HID + h * VDIM + v;
            wr_planes(ohi, olo, oidx, vout);
        }
    }
}

// ---------------- bf16x3 GEMM, cp.async 3-stage + ldmatrix -------------------
#define KST 40
#define ST_A 5120
#define ST_W 2560
#define ST_TOT (2 * ST_A + 2 * ST_W)
#define GSMEM (3 * ST_TOT * 2)

__global__ __launch_bounds__(256, 2) void k_gemm_mma(
    const __nv_bfloat16* __restrict__ Ahi, const __nv_bfloat16* __restrict__ Alo,
    const __nv_bfloat16* __restrict__ Whi, const __nv_bfloat16* __restrict__ Wlo,
    const __nv_bfloat16* __restrict__ A2hi, const __nv_bfloat16* __restrict__ A2lo,
    const __nv_bfloat16* __restrict__ W2hi, const __nv_bfloat16* __restrict__ W2lo,
    const float* __restrict__ bias, const float* __restrict__ bias2,
    float* __restrict__ C, __nv_bfloat16* __restrict__ Chi, __nv_bfloat16* __restrict__ Clo,
    int M, int N, int K1, int K2, int dogelu) {
    extern __shared__ __nv_bfloat16 sm[];

    int bm = blockIdx.x * 128, bn = blockIdx.y * 64;
    int tid = threadIdx.x;
    int warp = tid >> 5, lane = tid & 31;
    int wm = warp & 1, wn = warp >> 1;
    int lr = lane >> 2, lc = lane & 3;

    float acc[4][2][4];
#pragma unroll
    for (int i = 0; i < 4; i++)
#pragma unroll
        for (int j = 0; j < 2; j++)
#pragma unroll
            for (int t = 0; t < 4; t++) acc[i][j][t] = 0.0f;

    int rA0 = tid >> 2, cA0 = (tid & 3) * 8;
    int rA1 = rA0 + 64;
    int rW = tid >> 2, cW = (tid & 3) * 8;

    int NT1 = K1 / 32;
    int NT = NT1 + K2 / 32;

    unsigned smem_u32 = (unsigned)__cvta_generic_to_shared(sm);
    unsigned laneA = (unsigned)((wm * 64 + (lane & 15)) * KST * 2 + ((lane >> 4) & 1) * 16);
    unsigned laneB = (unsigned)((wn * 16 + ((lane >> 4) & 1) * 8 + (lane & 7)) * KST * 2
                                + ((lane >> 3) & 1) * 16);

    auto issue = [&](int nt_) {
        __nv_bfloat16* base = sm + (nt_ % 3) * ST_TOT;
        const __nv_bfloat16 *ah, *al, *wh, *wl;
        int K, kof;
        if (nt_ < NT1) { ah = Ahi; al = Alo; wh = Whi; wl = Wlo; K = K1; kof = nt_ * 32; }
        else { ah = A2hi; al = A2lo; wh = W2hi; wl = W2lo; K = K2; kof = (nt_ - NT1) * 32; }
        size_t g0 = (size_t)(bm + rA0) * K + kof + cA0;
        size_t g1 = (size_t)(bm + rA1) * K + kof + cA0;
        size_t gw = (size_t)(bn + rW) * K + kof + cW;
        cp16(base + rA0 * KST + cA0, ah + g0);
        cp16(base + rA1 * KST + cA0, ah + g1);
        cp16(base + ST_A + rA0 * KST + cA0, al + g0);
        cp16(base + ST_A + rA1 * KST + cA0, al + g1);
        cp16(base + 2 * ST_A + rW * KST + cW, wh + gw);
        cp16(base + 2 * ST_A + ST_W + rW * KST + cW, wl + gw);
    };

    issue(0); CP_COMMIT();
    issue(1); CP_COMMIT();
    CP_WAIT(1);
    __syncthreads();

    for (int kt = 0; kt < NT; kt++) {
        unsigned stage = smem_u32 + (unsigned)((kt % 3) * ST_TOT * 2);
        unsigned aH = stage + laneA;
        unsigned aL = aH + ST_A * 2;
        unsigned bH = stage + 2 * ST_A * 2 + laneB;
        unsigned bL = bH + ST_W * 2;
#pragma unroll
        for (int kk = 0; kk < 2; kk++) {
            unsigned kb = (unsigned)(kk * 32);
            unsigned ah[4][4], al[4][4], bh[2][2], bl[2][2];
#pragma unroll
            for (int mt = 0; mt < 4; mt++) ldm_x4(ah[mt], aH + mt * (16 * KST * 2) + kb);
#pragma unroll
            for (int mt = 0; mt < 4; mt++) ldm_x4(al[mt], aL + mt * (16 * KST * 2) + kb);
            {
                unsigned t[4];
                ldm_x4(t, bH + kb);
                bh[0][0] = t[0]; bh[0][1] = t[1]; bh[1][0] = t[2]; bh[1][1] = t[3];
                ldm_x4(t, bL + kb);
                bl[0][0] = t[0]; bl[0][1] = t[1]; bl[1][0] = t[2]; bl[1][1] = t[3];
            }
#pragma unroll
            for (int mt = 0; mt < 4; mt++)
#pragma unroll
                for (int nt = 0; nt < 2; nt++) {
                    mma16(acc[mt][nt], al[mt], bh[nt]);
                    mma16(acc[mt][nt], ah[mt], bl[nt]);
                    mma16(acc[mt][nt], ah[mt], bh[nt]);
                }
        }
        if (kt + 2 < NT) {
            issue(kt + 2); CP_COMMIT();
            CP_WAIT(1);
        } else if (kt + 1 < NT) {
            CP_WAIT(0);
        }
        __syncthreads();
    }

#pragma unroll
    for (int mt = 0; mt < 4; mt++) {
        int r0 = bm + wm * 64 + mt * 16 + lr;
        int r1 = r0 + 8;
#pragma unroll
        for (int nt = 0; nt < 2; nt++) {
            int col = bn + wn * 16 + nt * 8 + 2 * lc;
            float2 b2 = make_float2(0.f, 0.f);
            if (bias) b2 = *(const float2*)(bias + col);
            if (bias2) {
                float2 e2 = *(const float2*)(bias2 + col);
                b2.x += e2.x; b2.y += e2.y;
            }
            float2 v0, v1;
            v0.x = acc[mt][nt][0] + b2.x; v0.y = acc[mt][nt][1] + b2.y;
            v1.x = acc[mt][nt][2] + b2.x; v1.y = acc[mt][nt][3] + b2.y;
            if (dogelu) {
                v0.x = gelu_f(v0.x); v0.y = gelu_f(v0.y);
                v1.x = gelu_f(v1.x); v1.y = gelu_f(v1.y);
            }
            if (C) {
                *(float2*)(C + (size_t)r0 * N + col) = v0;
                *(float2*)(C + (size_t)r1 * N + col) = v1;
            }
            if (Chi) {
                wr_planes(Chi, Clo, (size_t)r0 * N + col, v0.x);
                wr_planes(Chi, Clo, (size_t)r0 * N + col + 1, v0.y);
                wr_planes(Chi, Clo, (size_t)r1 * N + col, v1.x);
                wr_planes(Chi, Clo, (size_t)r1 * N + col + 1, v1.y);
            }
        }
    }
}

// final linear HID->1
__global__ void k_fc2(const float* __restrict__ h, const float* __restrict__ w,
                      const float* __restrict__ b, float* __restrict__ out) {
    int row = blockIdx.x * 8 + (threadIdx.x >> 5);
    int lane = threadIdx.x & 31;
    const float* hr = h + (size_t)row * HID;
    float acc = 0.0f;
#pragma unroll
    for (int o = lane; o < HID; o += 32) acc = fmaf(hr[o], w[o], acc);
#pragma unroll
    for (int s = 16; s > 0; s >>= 1) acc += __shfl_xor_sync(0xffffffffu, acc, s);
    if (lane == 0) out[row] = acc + b[0];
}

struct Planes { __nv_bfloat16 *hi, *lo; };

static inline void gemm(Planes A, Planes W, const float* bias,
                        float* C, Planes Cp, int M, int N, int K, int g) {
    dim3 gr(M / 128, N / 64);
    k_gemm_mma<<<gr, 256, GSMEM>>>(A.hi, A.lo, W.hi, W.lo, 0, 0, 0, 0,
                                   bias, 0, C, Cp.hi, Cp.lo, M, N, K, 0, g);
}

static inline void gemm2(Planes A, Planes W, Planes A2, Planes W2,
                         const float* bias, const float* bias2,
                         float* C, Planes Cp, int M, int N, int K1, int K2, int g) {
    dim3 gr(M / 128, N / 64);
    k_gemm_mma<<<gr, 256, GSMEM>>>(A.hi, A.lo, W.hi, W.lo, A2.hi, A2.lo, W2.hi, W2.lo,
                                   bias, bias2, C, Cp.hi, Cp.lo, M, N, K1, K2, g);
}

extern "C" void kernel_launch(void* const* d_in, const int* in_sizes, int n_in,
                              void* d_out, int out_size) {
    const float* x      = (const float*)d_in[0];
    const float* enw    = (const float*)d_in[1];
    const float* enb    = (const float*)d_in[2];
    const float* down_r = (const float*)d_in[3];
    const float* down_w = (const float*)d_in[4];
    const float* pa_r   = (const float*)d_in[5];
    const float* pa_w   = (const float*)d_in[6];
    const float* mlp1_w = (const float*)d_in[7];
    const float* mlp1_b = (const float*)d_in[8];
    const float* mlp2_w = (const float*)d_in[9];
    const float* mlp2_b = (const float*)d_in[10];
    const float* res_w  = (const float*)d_in[11];
    const float* res_b  = (const float*)d_in[12];
    const float* up_r   = (const float*)d_in[13];
    const float* up_w   = (const float*)d_in[14];
    const float* de1w   = (const float*)d_in[15];
    const float* de1b   = (const float*)d_in[16];
    const float* de2w   = (const float*)d_in[17];
    const float* de2b   = (const float*)d_in[18];
    float* out = (float*)d_out;

    static int attr_set = 0;
    if (!attr_set) {
        cudaFuncSetAttribute(k_gemm_mma, cudaFuncAttributeMaxDynamicSharedMemorySize, GSMEM);
        attr_set = 1;
    }

    float *bufA, *bufB, *la, *ex, *ey, *rsx, *rsy, *dst_d, *dst_p;
    int *idx_d, *cnt_d, *idx_p, *cnt_p;
    __nv_bfloat16 *whi, *wlo;
    Planes pA, plb, plc, plh, pld;
    cudaGetSymbolAddress((void**)&bufA, g_bufA);
    cudaGetSymbolAddress((void**)&bufB, g_bufB);
    cudaGetSymbolAddress((void**)&la, g_la);
    cudaGetSymbolAddress((void**)&ex, g_ex);
    cudaGetSymbolAddress((void**)&ey, g_ey);
    cudaGetSymbolAddress((void**)&rsx, g_rsx);
    cudaGetSymbolAddress((void**)&rsy, g_rsy);
    cudaGetSymbolAddress((void**)&dst_d, g_dst_d);
    cudaGetSymbolAddress((void**)&dst_p, g_dst_p);
    cudaGetSymbolAddress((void**)&idx_d, g_idx_d);
    cudaGetSymbolAddress((void**)&cnt_d, g_cnt_d);
    cudaGetSymbolAddress((void**)&idx_p, g_idx_p);
    cudaGetSymbolAddress((void**)&cnt_p, g_cnt_p);
    cudaGetSymbolAddress((void**)&whi, g_whi);
    cudaGetSymbolAddress((void**)&wlo, g_wlo);
    cudaGetSymbolAddress((void**)&pA.hi, g_Ahi);
    cudaGetSymbolAddress((void**)&pA.lo, g_Alo);
    cudaGetSymbolAddress((void**)&plb.hi, g_lbhi);
    cudaGetSymbolAddress((void**)&plb.lo, g_lblo);
    cudaGetSymbolAddress((void**)&plc.hi, g_lchi);
    cudaGetSymbolAddress((void**)&plc.lo, g_lclo);
    cudaGetSymbolAddress((void**)&plh.hi, g_lhhi);
    cudaGetSymbolAddress((void**)&plh.lo, g_lhlo);
    cudaGetSymbolAddress((void**)&pld.hi, g_ldhi);
    cudaGetSymbolAddress((void**)&pld.lo, g_ldlo);

    Planes pnull = {0, 0};
    auto wslot = [&](int s) { Planes p = {whi + (size_t)s * 65536, wlo + (size_t)s * 65536}; return p; };

    // 1 fused init (wconv + encoder)
    k_init<<<WB + BATCH * NI, 256>>>(down_w, pa_w, up_w, mlp1_w, mlp2_w, res_w, de1w,
                                     whi, wlo, x, enw, enb, bufA, pA.hi, pA.lo);
    // 2 thresh_down
    {
        double id = 0.02 * (double)(NI - 1);
        int k0 = (int)id;
        k_thresh<NI, 32, 64, 2, 7938><<<NL, 256>>>(1.0f / 8192.0f, k0,
                                                   (float)(id - k0), idx_d, dst_d, cnt_d);
    }
    // 3 big value GEMM
    gemm(pA, wslot(0), 0, bufB, pnull, BATCH * NI, HID, HID, 0);
    // 4 down attention  <-- profiled slot
    k_att_sparse<<<dim3(NL, NHEAD), 256>>>(bufB, down_r, idx_d, dst_d, cnt_d,
                                           plh.hi, plh.lo, NI, NL);
    // 5 thresh_proc
    {
        double ip = 0.10 * (double)(NL - 1);
        int k0p = (int)ip;
        k_thresh<NL, 32, 32, 1, 1922><<<NL, 256>>>(1.0f / 2048.0f, k0p,
                                                   (float)(ip - k0p), idx_p, dst_p, cnt_p);
    }

    // processor blocks: planes alternate plh <-> pld
    Planes phc = plh, phn = pld;
    for (int i = 0; i < NBLK; i++) {
        gemm(phc, wslot(1 + i), 0, la, pnull, BATCH * NL, HID, HID, 0);
        k_att_sparse<<<dim3(NL, NHEAD), 256>>>(la, pa_r + i * NHEAD, idx_p, dst_p, cnt_p,
                                               plb.hi, plb.lo, NL, NL);
        gemm(plb, wslot(6 + i), mlp1_b + i * HID, 0, plc, BATCH * NL, HID, HID, 1);
        gemm2(plc, wslot(10 + i), phc, wslot(14 + i),
              mlp2_b + i * HID, res_b + i * HID, 0, phn, BATCH * NL, HID, HID, HID, 1);
        Planes tp = phc; phc = phn; phn = tp;
    }

    // up attention (separable)
    gemm(phc, wslot(5), 0, la, pnull, BATCH * NL, HID, HID, 0);
    k_up_exp<<<NHEAD, 256>>>(up_r, ex, ey, rsx, rsy);
    k_up_s1<<<dim3(32, NHEAD), 256>>>(la, ey, bufB);
    k_up_s2<<<dim3(64, NHEAD), 256>>>(bufB, ex, rsx, rsy, pA.hi, pA.lo);

    // decoder
    gemm(pA, wslot(18), de1b, bufB, pnull, BATCH * NI, HID, HID, 1);
    k_fc2<<<BATCH * NI / 8, 256>>>(bufB, de2w, de2b, out);
}

// round 15
// speedup vs baseline: 1.4486x; 1.4486x over previous
#include <cuda_runtime.h>
#include <cuda_bf16.h>
#include <math.h>

#define HID   256
#define NHEAD 8
#define VDIM  32
#define BATCH 8
#define NI    4096
#define NL    1024
#define NO    4096
#define CAP   512
#define NBLK  4

// f32 scratch
__device__ float g_bufA[BATCH * NI * HID];
__device__ float g_bufB[BATCH * NI * HID];
__device__ float g_la[BATCH * NL * HID];
// bf16 hi/lo planes
#define WSLOTS 19
__device__ __nv_bfloat16 g_whi[WSLOTS * HID * HID];
__device__ __nv_bfloat16 g_wlo[WSLOTS * HID * HID];
__device__ __nv_bfloat16 g_Ahi[BATCH * NI * HID];
__device__ __nv_bfloat16 g_Alo[BATCH * NI * HID];
__device__ __nv_bfloat16 g_lbhi[BATCH * NL * HID];
__device__ __nv_bfloat16 g_lblo[BATCH * NL * HID];
__device__ __nv_bfloat16 g_lchi[BATCH * NL * HID];
__device__ __nv_bfloat16 g_lclo[BATCH * NL * HID];
__device__ __nv_bfloat16 g_lhhi[BATCH * NL * HID];
__device__ __nv_bfloat16 g_lhlo[BATCH * NL * HID];
__device__ __nv_bfloat16 g_ldhi[BATCH * NL * HID];
__device__ __nv_bfloat16 g_ldlo[BATCH * NL * HID];
// masks / tables
__device__ int   g_idx_d[NL * CAP];
__device__ float g_dst_d[NL * CAP];
__device__ int   g_cnt_d[NL];
__device__ int   g_idx_p[NL * CAP];
__device__ float g_dst_p[NL * CAP];
__device__ int   g_cnt_p[NL];
__device__ float g_ex[NHEAD * 64 * 32];
__device__ float g_ey[NHEAD * 64 * 32];
__device__ float g_rsx[NHEAD * 64];
__device__ float g_rsy[NHEAD * 64];
// precomputed head scales: [0..7] down, [8..39] pa blocks 0-3, [40..47] up
__device__ float g_sc[48];

__device__ __forceinline__ float gelu_f(float x) {
    float t = tanhf(0.7978845608028654f * (x + 0.044715f * x * x * x));
    return 0.5f * x * (1.0f + t);
}

__device__ __forceinline__ float head_scale(const float* r, int h) {
    float arg = 0.78539808485763197f * (1.0f + sinf(r[h]));
    return (float)tan((double)arg);
}

__device__ __forceinline__ void wr_planes(__nv_bfloat16* hi, __nv_bfloat16* lo,
                                          size_t idx, float v) {
    __nv_bfloat16 h = __float2bfloat16(v);
    hi[idx] = h;
    lo[idx] = __float2bfloat16(v - __bfloat162float(h));
}

__device__ __forceinline__ void mma16(float* c, const unsigned* a, const unsigned* b) {
    asm volatile(
        "mma.sync.aligned.m16n8k16.row.col.f32.bf16.bf16.f32 "
        "{%0,%1,%2,%3},{%4,%5,%6,%7},{%8,%9},{%0,%1,%2,%3};"
        : "+f"(c[0]), "+f"(c[1]), "+f"(c[2]), "+f"(c[3])
        : "r"(a[0]), "r"(a[1]), "r"(a[2]), "r"(a[3]), "r"(b[0]), "r"(b[1]));
}

__device__ __forceinline__ void ldm_x4(unsigned* r, unsigned addr) {
    asm volatile("ldmatrix.sync.aligned.m8n8.x4.shared.b16 {%0,%1,%2,%3}, [%4];"
        : "=r"(r[0]), "=r"(r[1]), "=r"(r[2]), "=r"(r[3]) : "r"(addr));
}

__device__ __forceinline__ void cp16(__nv_bfloat16* dst, const __nv_bfloat16* src) {
    unsigned d = (unsigned)__cvta_generic_to_shared(dst);
    asm volatile("cp.async.cg.shared.global [%0], [%1], 16;" :: "r"(d), "l"(src));
}
#define CP_COMMIT() asm volatile("cp.async.commit_group;")
#define CP_WAIT(N)  asm volatile("cp.async.wait_group %0;" :: "n"(N))

// ---------------- fused init: weight conversion + encoder + head scales -----
#define WB (WSLOTS * 65536 / 256)
#define EB (BATCH * NI)
__global__ void k_init(const float* __restrict__ down_w, const float* __restrict__ pa_w,
                       const float* __restrict__ up_w, const float* __restrict__ mlp1_w,
                       const float* __restrict__ mlp2_w, const float* __restrict__ res_w,
                       const float* __restrict__ de1w,
                       __nv_bfloat16* __restrict__ whi, __nv_bfloat16* __restrict__ wlo,
                       const float* __restrict__ x, const float* __restrict__ enw,
                       const float* __restrict__ enb, float* __restrict__ enc_out,
                       __nv_bfloat16* __restrict__ ohi, __nv_bfloat16* __restrict__ olo,
                       const float* __restrict__ down_r, const float* __restrict__ pa_r,
                       const float* __restrict__ up_r, float* __restrict__ sc) {
    if (blockIdx.x < WB) {
        int idx = blockIdx.x * 256 + threadIdx.x;
        int slot = idx >> 16;
        int e = idx & 65535;
        int n = e >> 8, k = e & 255;
        float v;
        if (slot == 0)      v = down_w[(n >> 5) * 8192 + k * 32 + (n & 31)];
        else if (slot <= 4) v = pa_w[(slot - 1) * 65536 + (n >> 5) * 8192 + k * 32 + (n & 31)];
        else if (slot == 5) v = up_w[(n >> 5) * 8192 + k * 32 + (n & 31)];
        else if (slot <= 9) v = mlp1_w[(slot - 6) * 65536 + e];
        else if (slot <= 13) v = mlp2_w[(slot - 10) * 65536 + e];
        else if (slot <= 17) v = res_w[(slot - 14) * 65536 + e];
        else                v = de1w[e];
        wr_planes(whi, wlo, idx, v);
    } else if (blockIdx.x < WB + EB) {
        size_t idx = (size_t)(blockIdx.x - WB) * 256 + threadIdx.x;
        size_t row = idx >> 8;
        int o = (int)(idx & 255);
        float acc = enb[o];
#pragma unroll
        for (int i = 0; i < 4; i++) acc = fmaf(x[row * 4 + i], enw[o * 4 + i], acc);
        float v = gelu_f(acc);
        enc_out[idx] = v;
        wr_planes(ohi, olo, idx, v);
    } else {
        int t = threadIdx.x;
        if (t < 8)       sc[t] = head_scale(down_r, t);
        else if (t < 40) sc[t] = head_scale(pa_r, t - 8);
        else if (t < 48) sc[t] = head_scale(up_r, t - 40);
    }
}

// -------- percentile threshold + survivor lists ------------------------------
template <int NK, int QRES, int KRES, int QM, int MAXD2>
__global__ void k_thresh(float invden, int k0, float frac,
                         int* __restrict__ idxL, float* __restrict__ dstL,
                         int* __restrict__ cnt) {
    __shared__ int hist[MAXD2 + 1];
    __shared__ int pre[256];
    __shared__ int s_lo, s_hi;
    __shared__ float s_thr;
    int q = blockIdx.x, tid = threadIdx.x;
    int qa = (q % QRES) * QM, qb = (q / QRES) * QM;
    for (int i = tid; i <= MAXD2; i += 256) hist[i] = 0;
    __syncthreads();
    for (int k = tid; k < NK; k += 256) {
        int a = qa - (k % KRES), b = qb - (k / KRES);
        atomicAdd(&hist[a * a + b * b], 1);
    }
    __syncthreads();
    const int len = (MAXD2 + 256) / 256;
    int s0 = tid * len;
    int e0 = s0 + len; if (e0 > MAXD2 + 1) e0 = MAXD2 + 1;
    int loc = 0;
    for (int i = s0; i < e0; i++) loc += hist[i];
    pre[tid] = loc;
    __syncthreads();
    for (int ofs = 1; ofs < 256; ofs <<= 1) {
        int v = (tid >= ofs) ? pre[tid - ofs] : 0;
        __syncthreads();
        pre[tid] += v;
        __syncthreads();
    }
    int incl = pre[tid], excl = incl - loc;
    int t1 = k0 + 1, t2 = k0 + 2;
    if (excl < t1 && incl >= t1) {
        int c = excl;
        for (int i = s0; i < e0; i++) { c += hist[i]; if (c >= t1) { s_lo = i; break; } }
    }
    if (excl < t2 && incl >= t2) {
        int c = excl;
        for (int i = s0; i < e0; i++) { c += hist[i]; if (c >= t2) { s_hi = i; break; } }
    }
    __syncthreads();
    if (tid == 0) {
        float flo = (float)s_lo * invden, fhi = (float)s_hi * invden;
        s_thr = flo + frac * (fhi - flo);
    }
    __syncthreads();
    if (tid < 32) {
        int lane = tid, c = 0;
        float thr = s_thr;
        for (int base = 0; base < NK; base += 32) {
            int k = base + lane;
            int a = qa - (k % KRES), b = qb - (k / KRES);
            float m = (float)(a * a + b * b) * invden;
            bool p = (m <= thr);
            unsigned mb = __ballot_sync(0xffffffffu, p);
            if (p) {
                int pos = c + __popc(mb & ((1u << lane) - 1u));
                if (pos < CAP) { idxL[q * CAP + pos] = k; dstL[q * CAP + pos] = m; }
            }
            c += __popc(mb);
        }
        if (lane == 0) cnt[q] = (c < CAP) ? c : CAP;
    }
}

// ---------------- sparse masked attention (precomputed scales) ----------------
__global__ __launch_bounds__(256) void k_att_sparse(
    const float* __restrict__ value, const float* __restrict__ sc,
    const int* __restrict__ idxL, const float* __restrict__ dstL,
    const int* __restrict__ cnt, __nv_bfloat16* __restrict__ ohi,
    __nv_bfloat16* __restrict__ olo, int NK_, int NQ_) {
    int q = blockIdx.x, h = blockIdx.y, tid = threadIdx.x;
    int n = cnt[q];
    float scale = sc[h];
    __shared__ float w_s[CAP];
    __shared__ int   i_s[CAP];
    __shared__ float red[256];
    float lsum = 0.0f;
    for (int j = tid; j < n; j += 256) {
        float e = expf(-__fmul_rn(dstL[q * CAP + j], scale));
        w_s[j] = e;
        i_s[j] = idxL[q * CAP + j];
        lsum += e;
    }
    red[tid] = lsum;
    __syncthreads();
    for (int s = 128; s > 0; s >>= 1) {
        if (tid < s) red[tid] += red[tid + s];
        __syncthreads();
    }
    float rden = 1.0f / red[0];
    int b = tid >> 5, v = tid & 31;
    const float* vb = value + (size_t)b * NK_ * HID + h * VDIM + v;
    float a0 = 0.f, a1 = 0.f, a2 = 0.f, a3 = 0.f;
    int j = 0;
    for (; j + 4 <= n; j += 4) {
        a0 = fmaf(w_s[j + 0], vb[(size_t)i_s[j + 0] * HID], a0);
        a1 = fmaf(w_s[j + 1], vb[(size_t)i_s[j + 1] * HID], a1);
        a2 = fmaf(w_s[j + 2], vb[(size_t)i_s[j + 2] * HID], a2);
        a3 = fmaf(w_s[j + 3], vb[(size_t)i_s[j + 3] * HID], a3);
    }
    for (; j < n; j++) a0 = fmaf(w_s[j], vb[(size_t)i_s[j] * HID], a0);
    float acc = (a0 + a1) + (a2 + a3);
    float vout = gelu_f(acc * rden);
    size_t oidx = ((size_t)(b * NQ_ + q)) * HID + h * VDIM + v;
    wr_planes(ohi, olo, oidx, vout);
}

// ---------------- up attention tables (precomputed scales) --------------------
__global__ void k_up_exp(const float* __restrict__ sc, float* __restrict__ ex,
                         float* __restrict__ ey, float* __restrict__ rsx,
                         float* __restrict__ rsy) {
    int h = blockIdx.x, tid = threadIdx.x;
    float scale = sc[h];
    for (int e = tid; e < 2048; e += 256) {
        int i = e >> 5, j = e & 31;
        int d = i - 2 * j, mn = i & 1;
        float v = expf(__fmul_rn((float)(mn - d * d) * (1.0f / 8192.0f), scale));
        ex[h * 2048 + e] = v;
        ey[h * 2048 + e] = v;
    }
    __syncthreads();
    if (tid < 64) {
        float s = 0.0f;
        for (int j = 0; j < 32; j++) s += ex[h * 2048 + tid * 32 + j];
        rsx[h * 64 + tid] = s;
        rsy[h * 64 + tid] = s;
    }
}

// Stage 1: contract ky
__global__ __launch_bounds__(256) void k_up_s1(const float* __restrict__ value,
                                               const float* __restrict__ ey,
                                               float* __restrict__ G1) {
    int kx = blockIdx.x, h = blockIdx.y, tid = threadIdx.x;
    __shared__ float eys[64][32];
    __shared__ float vs[32][256];
    for (int e = tid; e < 2048; e += 256) eys[e >> 5][e & 31] = ey[h * 2048 + e];
    int b = tid >> 5, v = tid & 31;
    const float* vp = value + ((size_t)b * NL + kx) * HID + h * VDIM + v;
#pragma unroll
    for (int ky = 0; ky < 32; ky++) vs[ky][tid] = vp[(size_t)ky * 32 * HID];
    __syncthreads();
    float* gp = G1 + ((size_t)h * 64 * 32 + kx) * 256 + tid;
#pragma unroll
    for (int qy = 0; qy < 64; qy += 4) {
        float a0 = 0.f, a1 = 0.f, a2 = 0.f, a3 = 0.f;
#pragma unroll
        for (int ky = 0; ky < 32; ky++) {
            float vv = vs[ky][tid];
            a0 = fmaf(eys[qy + 0][ky], vv, a0);
            a1 = fmaf(eys[qy + 1][ky], vv, a1);
            a2 = fmaf(eys[qy + 2][ky], vv, a2);
            a3 = fmaf(eys[qy + 3][ky], vv, a3);
        }
        gp[(size_t)(qy + 0) * 32 * 256] = a0;
        gp[(size_t)(qy + 1) * 32 * 256] = a1;
        gp[(size_t)(qy + 2) * 32 * 256] = a2;
        gp[(size_t)(qy + 3) * 32 * 256] = a3;
    }
}

// Stage 2: contract kx (plane output)
__global__ __launch_bounds__(256) void k_up_s2(const float* __restrict__ G1,
                                               const float* __restrict__ ex,
                                               const float* __restrict__ rsx,
                                               const float* __restrict__ rsy,
                                               __nv_bfloat16* __restrict__ ohi,
                                               __nv_bfloat16* __restrict__ olo) {
    int qy = blockIdx.x, h = blockIdx.y, tid = threadIdx.x;
    __shared__ float exs[64][32];
    __shared__ float gs[32][256];
    for (int e = tid; e < 2048; e += 256) exs[e >> 5][e & 31] = ex[h * 2048 + e];
    const float* gb = G1 + (size_t)(h * 64 + qy) * 32 * 256;
    for (int e = tid; e < 32 * 256; e += 256) gs[e >> 8][e & 255] = gb[e];
    __syncthreads();
    int b = tid >> 5, v = tid & 31;
    float sy = rsy[h * 64 + qy];
#pragma unroll
    for (int qx = 0; qx < 64; qx += 4) {
        float a0 = 0.f, a1 = 0.f, a2 = 0.f, a3 = 0.f;
#pragma unroll
        for (int kx = 0; kx < 32; kx++) {
            float g = gs[kx][tid];
            a0 = fmaf(exs[qx + 0][kx], g, a0);
            a1 = fmaf(exs[qx + 1][kx], g, a1);
            a2 = fmaf(exs[qx + 2][kx], g, a2);
            a3 = fmaf(exs[qx + 3][kx], g, a3);
        }
#pragma unroll
        for (int i = 0; i < 4; i++) {
            float acc = (i == 0) ? a0 : (i == 1) ? a1 : (i == 2) ? a2 : a3;
            float rdv = 1.0f / (rsx[h * 64 + qx + i] * sy);
            float vout = gelu_f(acc * rdv);
            size_t oidx = ((size_t)b * NO + qy * 64 + qx + i) * HID + h * VDIM + v;
            wr_planes(ohi, olo, oidx, vout);
        }
    }
}

// ---------------- bf16x3 GEMM, cp.async 3-stage + ldmatrix -------------------
#define KST 40
#define ST_A 5120
#define ST_W 2560
#define ST_TOT (2 * ST_A + 2 * ST_W)
#define GSMEM (3 * ST_TOT * 2)

__global__ __launch_bounds__(256, 2) void k_gemm_mma(
    const __nv_bfloat16* __restrict__ Ahi, const __nv_bfloat16* __restrict__ Alo,
    const __nv_bfloat16* __restrict__ Whi, const __nv_bfloat16* __restrict__ Wlo,
    const __nv_bfloat16* __restrict__ A2hi, const __nv_bfloat16* __restrict__ A2lo,
    const __nv_bfloat16* __restrict__ W2hi, const __nv_bfloat16* __restrict__ W2lo,
    const float* __restrict__ bias, const float* __restrict__ bias2,
    float* __restrict__ C, __nv_bfloat16* __restrict__ Chi, __nv_bfloat16* __restrict__ Clo,
    int M, int N, int K1, int K2, int dogelu) {
    extern __shared__ __nv_bfloat16 sm[];

    int bm = blockIdx.x * 128, bn = blockIdx.y * 64;
    int tid = threadIdx.x;
    int warp = tid >> 5, lane = tid & 31;
    int wm = warp & 1, wn = warp >> 1;
    int lr = lane >> 2, lc = lane & 3;

    float acc[4][2][4];
#pragma unroll
    for (int i = 0; i < 4; i++)
#pragma unroll
        for (int j = 0; j < 2; j++)
#pragma unroll
            for (int t = 0; t < 4; t++) acc[i][j][t] = 0.0f;

    int rA0 = tid >> 2, cA0 = (tid & 3) * 8;
    int rA1 = rA0 + 64;
    int rW = tid >> 2, cW = (tid & 3) * 8;

    int NT1 = K1 / 32;
    int NT = NT1 + K2 / 32;

    unsigned smem_u32 = (unsigned)__cvta_generic_to_shared(sm);
    unsigned laneA = (unsigned)((wm * 64 + (lane & 15)) * KST * 2 + ((lane >> 4) & 1) * 16);
    unsigned laneB = (unsigned)((wn * 16 + ((lane >> 4) & 1) * 8 + (lane & 7)) * KST * 2
                                + ((lane >> 3) & 1) * 16);

    auto issue = [&](int nt_) {
        __nv_bfloat16* base = sm + (nt_ % 3) * ST_TOT;
        const __nv_bfloat16 *ah, *al, *wh, *wl;
        int K, kof;
        if (nt_ < NT1) { ah = Ahi; al = Alo; wh = Whi; wl = Wlo; K = K1; kof = nt_ * 32; }
        else { ah = A2hi; al = A2lo; wh = W2hi; wl = W2lo; K = K2; kof = (nt_ - NT1) * 32; }
        size_t g0 = (size_t)(bm + rA0) * K + kof + cA0;
        size_t g1 = (size_t)(bm + rA1) * K + kof + cA0;
        size_t gw = (size_t)(bn + rW) * K + kof + cW;
        cp16(base + rA0 * KST + cA0, ah + g0);
        cp16(base + rA1 * KST + cA0, ah + g1);
        cp16(base + ST_A + rA0 * KST + cA0, al + g0);
        cp16(base + ST_A + rA1 * KST + cA0, al + g1);
        cp16(base + 2 * ST_A + rW * KST + cW, wh + gw);
        cp16(base + 2 * ST_A + ST_W + rW * KST + cW, wl + gw);
    };

    issue(0); CP_COMMIT();
    issue(1); CP_COMMIT();
    CP_WAIT(1);
    __syncthreads();

    for (int kt = 0; kt < NT; kt++) {
        unsigned stage = smem_u32 + (unsigned)((kt % 3) * ST_TOT * 2);
        unsigned aH = stage + laneA;
        unsigned aL = aH + ST_A * 2;
        unsigned bH = stage + 2 * ST_A * 2 + laneB;
        unsigned bL = bH + ST_W * 2;
#pragma unroll
        for (int kk = 0; kk < 2; kk++) {
            unsigned kb = (unsigned)(kk * 32);
            unsigned ah[4][4], al[4][4], bh[2][2], bl[2][2];
#pragma unroll
            for (int mt = 0; mt < 4; mt++) ldm_x4(ah[mt], aH + mt * (16 * KST * 2) + kb);
#pragma unroll
            for (int mt = 0; mt < 4; mt++) ldm_x4(al[mt], aL + mt * (16 * KST * 2) + kb);
            {
                unsigned t[4];
                ldm_x4(t, bH + kb);
                bh[0][0] = t[0]; bh[0][1] = t[1]; bh[1][0] = t[2]; bh[1][1] = t[3];
                ldm_x4(t, bL + kb);
                bl[0][0] = t[0]; bl[0][1] = t[1]; bl[1][0] = t[2]; bl[1][1] = t[3];
            }
#pragma unroll
            for (int mt = 0; mt < 4; mt++)
#pragma unroll
                for (int nt = 0; nt < 2; nt++) {
                    mma16(acc[mt][nt], al[mt], bh[nt]);
                    mma16(acc[mt][nt], ah[mt], bl[nt]);
                    mma16(acc[mt][nt], ah[mt], bh[nt]);
                }
        }
        if (kt + 2 < NT) {
            issue(kt + 2); CP_COMMIT();
            CP_WAIT(1);
        } else if (kt + 1 < NT) {
            CP_WAIT(0);
        }
        __syncthreads();
    }

#pragma unroll
    for (int mt = 0; mt < 4; mt++) {
        int r0 = bm + wm * 64 + mt * 16 + lr;
        int r1 = r0 + 8;
#pragma unroll
        for (int nt = 0; nt < 2; nt++) {
            int col = bn + wn * 16 + nt * 8 + 2 * lc;
            float2 b2 = make_float2(0.f, 0.f);
            if (bias) b2 = *(const float2*)(bias + col);
            if (bias2) {
                float2 e2 = *(const float2*)(bias2 + col);
                b2.x += e2.x; b2.y += e2.y;
            }
            float2 v0, v1;
            v0.x = acc[mt][nt][0] + b2.x; v0.y = acc[mt][nt][1] + b2.y;
            v1.x = acc[mt][nt][2] + b2.x; v1.y = acc[mt][nt][3] + b2.y;
            if (dogelu) {
                v0.x = gelu_f(v0.x); v0.y = gelu_f(v0.y);
                v1.x = gelu_f(v1.x); v1.y = gelu_f(v1.y);
            }
            if (C) {
                *(float2*)(C + (size_t)r0 * N + col) = v0;
                *(float2*)(C + (size_t)r1 * N + col) = v1;
            }
            if (Chi) {
                wr_planes(Chi, Clo, (size_t)r0 * N + col, v0.x);
                wr_planes(Chi, Clo, (size_t)r0 * N + col + 1, v0.y);
                wr_planes(Chi, Clo, (size_t)r1 * N + col, v1.x);
                wr_planes(Chi, Clo, (size_t)r1 * N + col + 1, v1.y);
            }
        }
    }
}

// final linear HID->1
__global__ void k_fc2(const float* __restrict__ h, const float* __restrict__ w,
                      const float* __restrict__ b, float* __restrict__ out) {
    int row = blockIdx.x * 8 + (threadIdx.x >> 5);
    int lane = threadIdx.x & 31;
    const float* hr = h + (size_t)row * HID;
    float acc = 0.0f;
#pragma unroll
    for (int o = lane; o < HID; o += 32) acc = fmaf(hr[o], w[o], acc);
#pragma unroll
    for (int s = 16; s > 0; s >>= 1) acc += __shfl_xor_sync(0xffffffffu, acc, s);
    if (lane == 0) out[row] = acc + b[0];
}

struct Planes { __nv_bfloat16 *hi, *lo; };

static inline void gemm(Planes A, Planes W, const float* bias,
                        float* C, Planes Cp, int M, int N, int K, int g) {
    dim3 gr(M / 128, N / 64);
    k_gemm_mma<<<gr, 256, GSMEM>>>(A.hi, A.lo, W.hi, W.lo, 0, 0, 0, 0,
                                   bias, 0, C, Cp.hi, Cp.lo, M, N, K, 0, g);
}

static inline void gemm2(Planes A, Planes W, Planes A2, Planes W2,
                         const float* bias, const float* bias2,
                         float* C, Planes Cp, int M, int N, int K1, int K2, int g) {
    dim3 gr(M / 128, N / 64);
    k_gemm_mma<<<gr, 256, GSMEM>>>(A.hi, A.lo, W.hi, W.lo, A2.hi, A2.lo, W2.hi, W2.lo,
                                   bias, bias2, C, Cp.hi, Cp.lo, M, N, K1, K2, g);
}

extern "C" void kernel_launch(void* const* d_in, const int* in_sizes, int n_in,
                              void* d_out, int out_size) {
    const float* x      = (const float*)d_in[0];
    const float* enw    = (const float*)d_in[1];
    const float* enb    = (const float*)d_in[2];
    const float* down_r = (const float*)d_in[3];
    const float* down_w = (const float*)d_in[4];
    const float* pa_r   = (const float*)d_in[5];
    const float* pa_w   = (const float*)d_in[6];
    const float* mlp1_w = (const float*)d_in[7];
    const float* mlp1_b = (const float*)d_in[8];
    const float* mlp2_w = (const float*)d_in[9];
    const float* mlp2_b = (const float*)d_in[10];
    const float* res_w  = (const float*)d_in[11];
    const float* res_b  = (const float*)d_in[12];
    const float* up_r   = (const float*)d_in[13];
    const float* up_w   = (const float*)d_in[14];
    const float* de1w   = (const float*)d_in[15];
    const float* de1b   = (const float*)d_in[16];
    const float* de2w   = (const float*)d_in[17];
    const float* de2b   = (const float*)d_in[18];
    float* out = (float*)d_out;

    static int attr_set = 0;
    if (!attr_set) {
        cudaFuncSetAttribute(k_gemm_mma, cudaFuncAttributeMaxDynamicSharedMemorySize, GSMEM);
        attr_set = 1;
    }

    float *bufA, *bufB, *la, *ex, *ey, *rsx, *rsy, *dst_d, *dst_p, *scp;
    int *idx_d, *cnt_d, *idx_p, *cnt_p;
    __nv_bfloat16 *whi, *wlo;
    Planes pA, plb, plc, plh, pld;
    cudaGetSymbolAddress((void**)&bufA, g_bufA);
    cudaGetSymbolAddress((void**)&bufB, g_bufB);
    cudaGetSymbolAddress((void**)&la, g_la);
    cudaGetSymbolAddress((void**)&ex, g_ex);
    cudaGetSymbolAddress((void**)&ey, g_ey);
    cudaGetSymbolAddress((void**)&rsx, g_rsx);
    cudaGetSymbolAddress((void**)&rsy, g_rsy);
    cudaGetSymbolAddress((void**)&dst_d, g_dst_d);
    cudaGetSymbolAddress((void**)&dst_p, g_dst_p);
    cudaGetSymbolAddress((void**)&idx_d, g_idx_d);
    cudaGetSymbolAddress((void**)&cnt_d, g_cnt_d);
    cudaGetSymbolAddress((void**)&idx_p, g_idx_p);
    cudaGetSymbolAddress((void**)&cnt_p, g_cnt_p);
    cudaGetSymbolAddress((void**)&scp, g_sc);
    cudaGetSymbolAddress((void**)&whi, g_whi);
    cudaGetSymbolAddress((void**)&wlo, g_wlo);
    cudaGetSymbolAddress((void**)&pA.hi, g_Ahi);
    cudaGetSymbolAddress((void**)&pA.lo, g_Alo);
    cudaGetSymbolAddress((void**)&plb.hi, g_lbhi);
    cudaGetSymbolAddress((void**)&plb.lo, g_lblo);
    cudaGetSymbolAddress((void**)&plc.hi, g_lchi);
    cudaGetSymbolAddress((void**)&plc.lo, g_lclo);
    cudaGetSymbolAddress((void**)&plh.hi, g_lhhi);
    cudaGetSymbolAddress((void**)&plh.lo, g_lhlo);
    cudaGetSymbolAddress((void**)&pld.hi, g_ldhi);
    cudaGetSymbolAddress((void**)&pld.lo, g_ldlo);

    Planes pnull = {0, 0};
    auto wslot = [&](int s) { Planes p = {whi + (size_t)s * 65536, wlo + (size_t)s * 65536}; return p; };

    // 1 fused init (wconv + encoder + head scales)
    k_init<<<WB + EB + 1, 256>>>(down_w, pa_w, up_w, mlp1_w, mlp2_w, res_w, de1w,
                                 whi, wlo, x, enw, enb, bufA, pA.hi, pA.lo,
                                 down_r, pa_r, up_r, scp);
    // 2 thresh_down
    {
        double id = 0.02 * (double)(NI - 1);
        int k0 = (int)id;
        k_thresh<NI, 32, 64, 2, 7938><<<NL, 256>>>(1.0f / 8192.0f, k0,
                                                   (float)(id - k0), idx_d, dst_d, cnt_d);
    }
    // 3 big value GEMM
    gemm(pA, wslot(0), 0, bufB, pnull, BATCH * NI, HID, HID, 0);
    // 4 down attention  <-- profiled slot
    k_att_sparse<<<dim3(NL, NHEAD), 256>>>(bufB, scp, idx_d, dst_d, cnt_d,
                                           plh.hi, plh.lo, NI, NL);
    // 5 thresh_proc
    {
        double ip = 0.10 * (double)(NL - 1);
        int k0p = (int)ip;
        k_thresh<NL, 32, 32, 1, 1922><<<NL, 256>>>(1.0f / 2048.0f, k0p,
                                                   (float)(ip - k0p), idx_p, dst_p, cnt_p);
    }

    // processor blocks: planes alternate plh <-> pld
    Planes phc = plh, phn = pld;
    for (int i = 0; i < NBLK; i++) {
        gemm(phc, wslot(1 + i), 0, la, pnull, BATCH * NL, HID, HID, 0);
        k_att_sparse<<<dim3(NL, NHEAD), 256>>>(la, scp + 8 + i * NHEAD, idx_p, dst_p, cnt_p,
                                               plb.hi, plb.lo, NL, NL);
        gemm(plb, wslot(6 + i), mlp1_b + i * HID, 0, plc, BATCH * NL, HID, HID, 1);
        gemm2(plc, wslot(10 + i), phc, wslot(14 + i),
              mlp2_b + i * HID, res_b + i * HID, 0, phn, BATCH * NL, HID, HID, HID, 1);
        Planes tp = phc; phc = phn; phn = tp;
    }

    // up attention (separable)
    gemm(phc, wslot(5), 0, la, pnull, BATCH * NL, HID, HID, 0);
    k_up_exp<<<NHEAD, 256>>>(scp + 40, ex, ey, rsx, rsy);
    k_up_s1<<<dim3(32, NHEAD), 256>>>(la, ey, bufB);
    k_up_s2<<<dim3(64, NHEAD), 256>>>(bufB, ex, rsx, rsy, pA.hi, pA.lo);

    // decoder
    gemm(pA, wslot(18), de1b, bufB, pnull, BATCH * NI, HID, HID, 1);
    k_fc2<<<BATCH * NI / 8, 256>>>(bufB, de2w, de2b, out);
}